// round 2
// baseline (speedup 1.0000x reference)
#include <cuda_runtime.h>
#include <math.h>

#define BATCH 8192
#define CH 128
#define NB 32
#define NH 4
#define HD 32
#define O3 384
#define ATT_SCALE 0.17677669529663687f  // 1/sqrt(32)

// ---- device scratch (no allocations allowed) ----
__device__ float  g_qkv_wT[CH * O3];   // [c][o] transposed qkv weights
__device__ float  g_out_wT[CH * CH];   // [c][o] transposed out weights
__device__ double g_bn_sum[CH];
__device__ double g_bn_sqs[CH];
__device__ float  g_bn_g[CH];
__device__ float  g_bn_b[CH];

// Transpose weights for coalesced lane=o reads; zero BN accumulators.
__global__ void prep_kernel(const float* __restrict__ qkv_w,
                            const float* __restrict__ out_w) {
    int i = blockIdx.x * blockDim.x + threadIdx.x;
    if (i < O3 * CH) {
        int o = i / CH, c = i % CH;           // qkv_w[o][c], row-major [384][128]
        g_qkv_wT[c * O3 + o] = qkv_w[i];
    }
    if (i < CH * CH) {
        int o = i / CH, c = i % CH;           // out_w[o][c], row-major [128][128]
        g_out_wT[c * CH + o] = out_w[i];
    }
    if (i < CH) { g_bn_sum[i] = 0.0; g_bn_sqs[i] = 0.0; }
}

// Shared memory layout (floats). Row stride 36 (=144B, 16B-aligned rows).
// No region is ever reused for two purposes.
#define XS_OFF   0        // xs  [128][36]  x[b], xs[c*36+n]
#define QK_OFF   4608     // qk  [384][36]  qkv natural: qk[o*36+n] (q:0-127,k:128-255,v:256-383)
#define AO_OFF   18432    // ao  [128][36]  attention out, ao[c*36+n]
#define YS_OFF   23040    // ys  [128][36]  pre-BN y staging
#define RP_OFF   27648    // rp  [4][63]    rel-pos transposed rp[h*63+p]
#define SMEM_FLOATS 27904 // 111,616 bytes

__global__ void __launch_bounds__(128, 2)
attn_kernel(const float* __restrict__ x,
            const float* __restrict__ qkv_b,
            const float* __restrict__ out_b,
            const float* __restrict__ remb,
            float* __restrict__ out) {
    extern __shared__ float sm[];
    float* xs = sm + XS_OFF;
    float* qk = sm + QK_OFF;
    float* ao = sm + AO_OFF;
    float* ys = sm + YS_OFF;
    float* rp = sm + RP_OFF;

    const int tid  = threadIdx.x;
    const int lane = tid & 31;
    const int wid  = tid >> 5;
    const int b    = blockIdx.x;

    // ---- stage x[b] into smem (coalesced float4 from gmem) ----
    const float4* xg = (const float4*)(x + (size_t)b * (CH * NB));
#pragma unroll
    for (int k = 0; k < 8; k++) {
        int f = tid + k * 128;               // float4 index 0..1023 of x[b]
        float4 v = xg[f];
        int c = f >> 3, n4 = f & 7;          // f = c*8 + n4
        *(float4*)(xs + c * 36 + n4 * 4) = v;
    }
    // rel_pos_emb [63][4] row-major -> rp[h*63 + p]
    for (int i = tid; i < (2 * NB - 1) * NH; i += 128) {
        int p = i >> 2, h = i & 3;           // remb[i] = remb[p][h]
        rp[h * 63 + p] = remb[i];
    }
    __syncthreads();

    // ---- Phase A: qkv[o][n] = sum_c qkv_w[o][c] * x[c][n] + qkv_b[o] ----
    // One uniform store path for q, k, v (natural layout).
    for (int t = wid; t < 12; t += 4) {
        int o = t * 32 + lane;
        float acc[32];
        float bias = qkv_b[o];
#pragma unroll
        for (int n = 0; n < 32; n++) acc[n] = bias;
#pragma unroll 4
        for (int c = 0; c < CH; c++) {
            float w = g_qkv_wT[c * O3 + o];                  // coalesced LDG
            const float4* xr = (const float4*)(xs + c * 36); // uniform broadcast
#pragma unroll
            for (int j = 0; j < 8; j++) {
                float4 xv = xr[j];
                acc[4*j+0] = fmaf(w, xv.x, acc[4*j+0]);
                acc[4*j+1] = fmaf(w, xv.y, acc[4*j+1]);
                acc[4*j+2] = fmaf(w, xv.z, acc[4*j+2]);
                acc[4*j+3] = fmaf(w, xv.w, acc[4*j+3]);
            }
        }
        float4* dst = (float4*)(qk + o * 36);
#pragma unroll
        for (int j = 0; j < 8; j++)
            dst[j] = make_float4(acc[4*j], acc[4*j+1], acc[4*j+2], acc[4*j+3]);
    }
    __syncthreads();

    // ---- Phase B: head h = wid, query bin n = lane ----
    // att[m] = sum_d q[h,d,n] * k[h,d,m]  (accumulate over d, float4 over m)
    {
        int h = wid;
        float qreg[32];
#pragma unroll
        for (int d = 0; d < 32; d++)
            qreg[d] = qk[(h * 32 + d) * 36 + lane];          // conflict-free
        float att[32];
#pragma unroll
        for (int m = 0; m < 32; m++) att[m] = 0.0f;
#pragma unroll 4
        for (int d = 0; d < 32; d++) {
            float qd = qreg[d];
            const float4* kr = (const float4*)(qk + (128 + h * 32 + d) * 36); // k[h,d,:]
#pragma unroll
            for (int j = 0; j < 8; j++) {
                float4 kv = kr[j];                            // uniform broadcast
                att[4*j+0] = fmaf(qd, kv.x, att[4*j+0]);
                att[4*j+1] = fmaf(qd, kv.y, att[4*j+1]);
                att[4*j+2] = fmaf(qd, kv.z, att[4*j+2]);
                att[4*j+3] = fmaf(qd, kv.w, att[4*j+3]);
            }
        }
        // bias + softmax over m (row lives in registers)
#pragma unroll
        for (int m = 0; m < 32; m++) {
            int idx = m - lane + (NB - 1);                    // (j - i) + 31
            idx = idx < 0 ? 0 : (idx > 2 * NB - 2 ? 2 * NB - 2 : idx);
            att[m] = fmaf(att[m], ATT_SCALE, rp[h * 63 + idx]);
        }
        float mx = att[0];
#pragma unroll
        for (int m = 1; m < 32; m++) mx = fmaxf(mx, att[m]);
        float ssum = 0.0f;
#pragma unroll
        for (int m = 0; m < 32; m++) {
            float e = __expf(att[m] - mx);
            att[m] = e;
            ssum += e;
        }
        float rs = 1.0f / ssum;
#pragma unroll
        for (int m = 0; m < 32; m++) att[m] *= rs;

        // ---- Phase C: ao[h*32+d][n] = sum_m att[m] * v[h,d,m] ----
#pragma unroll 2
        for (int d = 0; d < 32; d++) {
            const float4* vr = (const float4*)(qk + (256 + h * 32 + d) * 36); // v[h,d,:]
            float s0 = 0.0f, s1 = 0.0f, s2 = 0.0f, s3 = 0.0f;
#pragma unroll
            for (int j = 0; j < 8; j++) {
                float4 vv = vr[j];                            // uniform broadcast
                s0 = fmaf(att[4*j+0], vv.x, s0);
                s1 = fmaf(att[4*j+1], vv.y, s1);
                s2 = fmaf(att[4*j+2], vv.z, s2);
                s3 = fmaf(att[4*j+3], vv.w, s3);
            }
            ao[(h * 32 + d) * 36 + lane] = (s0 + s1) + (s2 + s3); // conflict-free
        }
    }
    __syncthreads();

    // ---- Phase D: y = out_w @ ao + out_b + x ; BN partial stats ----
    {
        int o = tid;                                          // channel 0..127
        float acc[32];
        float ob = out_b[o];
#pragma unroll
        for (int n = 0; n < 32; n++) acc[n] = ob;
#pragma unroll 4
        for (int c = 0; c < CH; c++) {
            float w = g_out_wT[c * CH + o];                   // coalesced LDG
            const float4* ar = (const float4*)(ao + c * 36);  // uniform broadcast
#pragma unroll
            for (int j = 0; j < 8; j++) {
                float4 av = ar[j];
                acc[4*j+0] = fmaf(w, av.x, acc[4*j+0]);
                acc[4*j+1] = fmaf(w, av.y, acc[4*j+1]);
                acc[4*j+2] = fmaf(w, av.z, acc[4*j+2]);
                acc[4*j+3] = fmaf(w, av.w, acc[4*j+3]);
            }
        }
        float s1 = 0.0f, s2 = 0.0f;
#pragma unroll
        for (int j = 0; j < 8; j++) {
            float4 xv = *(const float4*)(xs + o * 36 + 4 * j);  // residual
            float y0 = acc[4*j+0] + xv.x;
            float y1 = acc[4*j+1] + xv.y;
            float y2 = acc[4*j+2] + xv.z;
            float y3 = acc[4*j+3] + xv.w;
            s1 += (y0 + y1) + (y2 + y3);
            s2 = fmaf(y0, y0, s2); s2 = fmaf(y1, y1, s2);
            s2 = fmaf(y2, y2, s2); s2 = fmaf(y3, y3, s2);
            *(float4*)(ys + o * 36 + 4 * j) = make_float4(y0, y1, y2, y3);
        }
        atomicAdd(&g_bn_sum[o], (double)s1);
        atomicAdd(&g_bn_sqs[o], (double)s2);
    }
    __syncthreads();

    // ---- coalesced write of pre-BN y to gmem ----
    float4* og = (float4*)(out + (size_t)b * (CH * NB));
#pragma unroll
    for (int k = 0; k < 8; k++) {
        int f = tid + k * 128;
        int c = f >> 3, n4 = f & 7;
        og[f] = *(const float4*)(ys + c * 36 + n4 * 4);
    }
}

__global__ void bn_finalize(const float* __restrict__ gamma,
                            const float* __restrict__ beta) {
    int c = threadIdx.x;
    const double cnt = (double)BATCH * NB;
    double mean = g_bn_sum[c] / cnt;
    double var  = g_bn_sqs[c] / cnt - mean * mean;
    double inv  = 1.0 / sqrt(var + 1e-5);
    double g = (double)gamma[c] * inv;
    g_bn_g[c] = (float)g;
    g_bn_b[c] = (float)((double)beta[c] - mean * g);
}

__global__ void bn_apply(float* __restrict__ out) {
    int i = blockIdx.x * blockDim.x + threadIdx.x;  // global float4 index
    float4 v = ((const float4*)out)[i];
    int c = (i >> 3) & 127;                          // 8 float4 per channel row
    float g = g_bn_g[c], b = g_bn_b[c];
    v.x = fmaf(v.x, g, b);
    v.y = fmaf(v.y, g, b);
    v.z = fmaf(v.z, g, b);
    v.w = fmaf(v.w, g, b);
    ((float4*)out)[i] = v;
}

extern "C" void kernel_launch(void* const* d_in, const int* in_sizes, int n_in,
                              void* d_out, int out_size) {
    const float* x      = (const float*)d_in[0];
    const float* qkv_w  = (const float*)d_in[1];
    const float* qkv_b  = (const float*)d_in[2];
    const float* out_w  = (const float*)d_in[3];
    const float* out_b  = (const float*)d_in[4];
    const float* remb   = (const float*)d_in[5];
    const float* gamma  = (const float*)d_in[6];
    const float* beta   = (const float*)d_in[7];
    float* out = (float*)d_out;

    cudaFuncSetAttribute(attn_kernel, cudaFuncAttributeMaxDynamicSharedMemorySize,
                         SMEM_FLOATS * (int)sizeof(float));

    prep_kernel<<<192, 256>>>(qkv_w, out_w);
    attn_kernel<<<BATCH, 128, SMEM_FLOATS * sizeof(float)>>>(x, qkv_b, out_b, remb, out);
    bn_finalize<<<1, CH>>>(gamma, beta);
    bn_apply<<<(BATCH * CH * NB / 4) / 256, 256>>>(out);
}

// round 3
// speedup vs baseline: 1.1349x; 1.1349x over previous
#include <cuda_runtime.h>
#include <math.h>

#define BATCH 8192
#define CH 128
#define NB 32
#define NH 4
#define HD 32
#define O3 384
#define ATT_SCALE 0.17677669529663687f  // 1/sqrt(32)

typedef unsigned long long u64;

__device__ __forceinline__ u64 pack2(float lo, float hi) {
    u64 r; asm("mov.b64 %0, {%1, %2};" : "=l"(r) : "f"(lo), "f"(hi)); return r;
}
__device__ __forceinline__ void unpack2(u64 v, float& lo, float& hi) {
    asm("mov.b64 {%0, %1}, %2;" : "=f"(lo), "=f"(hi) : "l"(v));
}
__device__ __forceinline__ u64 ffma2(u64 a, u64 b, u64 c) {
    u64 d; asm("fma.rn.f32x2 %0, %1, %2, %3;" : "=l"(d) : "l"(a), "l"(b), "l"(c)); return d;
}
__device__ __forceinline__ u64 fadd2(u64 a, u64 b) {
    u64 d; asm("add.rn.f32x2 %0, %1, %2;" : "=l"(d) : "l"(a), "l"(b)); return d;
}

// ---- device scratch (no allocations allowed) ----
__device__ float  g_qkv_wT[CH * O3];   // [c][o]
__device__ float  g_out_wT[CH * CH];   // [c][o]
__device__ double g_bn_sum[CH];
__device__ double g_bn_sqs[CH];
__device__ float  g_bn_g[CH];
__device__ float  g_bn_b[CH];

__global__ void prep_kernel(const float* __restrict__ qkv_w,
                            const float* __restrict__ out_w) {
    int i = blockIdx.x * blockDim.x + threadIdx.x;
    if (i < O3 * CH) {
        int o = i / CH, c = i % CH;
        g_qkv_wT[c * O3 + o] = qkv_w[i];
    }
    if (i < CH * CH) {
        int o = i / CH, c = i % CH;
        g_out_wT[c * CH + o] = out_w[i];
    }
    if (i < CH) { g_bn_sum[i] = 0.0; g_bn_sqs[i] = 0.0; }
}

// Shared memory layout (floats). Row stride 36 floats = 144B (16B aligned).
#define XS_OFF   0        // xs  [128][36]
#define QK_OFF   4608     // qk  [384][36]  q:0-127, k:128-255, v:256-383 (natural [o][n])
#define AO_OFF   18432    // ao  [128][36]
#define YS_OFF   23040    // ys  [128][36]
#define RP_OFF   27648    // rp  [4][63]
#define SMEM_FLOATS 27904 // 111,616 bytes

__global__ void __launch_bounds__(128, 2)
attn_kernel(const float* __restrict__ x,
            const float* __restrict__ qkv_b,
            const float* __restrict__ out_b,
            const float* __restrict__ remb,
            float* __restrict__ out) {
    extern __shared__ float sm[];
    float* xs = sm + XS_OFF;
    float* qk = sm + QK_OFF;
    float* ao = sm + AO_OFF;
    float* ys = sm + YS_OFF;
    float* rp = sm + RP_OFF;

    const int tid  = threadIdx.x;
    const int lane = tid & 31;
    const int wid  = tid >> 5;
    const int b    = blockIdx.x;

    // ---- stage x[b] into smem ----
    const float4* xg = (const float4*)(x + (size_t)b * (CH * NB));
#pragma unroll
    for (int k = 0; k < 8; k++) {
        int f = tid + k * 128;
        float4 v = xg[f];
        int c = f >> 3, n4 = f & 7;
        *(float4*)(xs + c * 36 + n4 * 4) = v;
    }
    for (int i = tid; i < (2 * NB - 1) * NH; i += 128) {
        int p = i >> 2, h = i & 3;
        rp[h * 63 + p] = remb[i];
    }
    __syncthreads();

    // ---- Phase A: qkv[o][n] = sum_c W[o][c] * x[c][n] + b[o]  (packed f32x2) ----
    for (int t = wid; t < 12; t += 4) {
        int o = t * 32 + lane;
        float bias = qkv_b[o];
        u64 acc2[16];
        u64 b2 = pack2(bias, bias);
#pragma unroll
        for (int j = 0; j < 16; j++) acc2[j] = b2;
#pragma unroll 4
        for (int c = 0; c < CH; c++) {
            float w = g_qkv_wT[c * O3 + o];                       // coalesced LDG
            u64 w2 = pack2(w, w);
            const ulonglong2* xr = (const ulonglong2*)(xs + c * 36); // LDS.128 broadcast
#pragma unroll
            for (int j = 0; j < 8; j++) {
                ulonglong2 xv = xr[j];
                acc2[2*j+0] = ffma2(w2, xv.x, acc2[2*j+0]);
                acc2[2*j+1] = ffma2(w2, xv.y, acc2[2*j+1]);
            }
        }
        ulonglong2* dst = (ulonglong2*)(qk + o * 36);
#pragma unroll
        for (int j = 0; j < 8; j++)
            dst[j] = make_ulonglong2(acc2[2*j], acc2[2*j+1]);
    }
    __syncthreads();

    // ---- Phase B: head h = wid, query bin n = lane ----
    {
        int h = wid;
        float qreg[32];
#pragma unroll
        for (int d = 0; d < 32; d++)
            qreg[d] = qk[(h * 32 + d) * 36 + lane];               // conflict-free
        u64 att2[16];
#pragma unroll
        for (int j = 0; j < 16; j++) att2[j] = 0ull;
#pragma unroll 4
        for (int d = 0; d < 32; d++) {
            u64 qd2 = pack2(qreg[d], qreg[d]);
            const ulonglong2* kr = (const ulonglong2*)(qk + (128 + h * 32 + d) * 36);
#pragma unroll
            for (int j = 0; j < 8; j++) {
                ulonglong2 kv = kr[j];
                att2[2*j+0] = ffma2(qd2, kv.x, att2[2*j+0]);
                att2[2*j+1] = ffma2(qd2, kv.y, att2[2*j+1]);
            }
        }
        float att[32];
#pragma unroll
        for (int j = 0; j < 16; j++) unpack2(att2[j], att[2*j], att[2*j+1]);
#pragma unroll
        for (int m = 0; m < 32; m++) {
            int idx = m - lane + (NB - 1);
            idx = idx < 0 ? 0 : (idx > 2 * NB - 2 ? 2 * NB - 2 : idx);
            att[m] = fmaf(att[m], ATT_SCALE, rp[h * 63 + idx]);
        }
        float mx = att[0];
#pragma unroll
        for (int m = 1; m < 32; m++) mx = fmaxf(mx, att[m]);
        float ssum = 0.0f;
#pragma unroll
        for (int m = 0; m < 32; m++) {
            float e = __expf(att[m] - mx);
            att[m] = e;
            ssum += e;
        }
        float rs = 1.0f / ssum;
#pragma unroll
        for (int m = 0; m < 32; m++) att[m] *= rs;
#pragma unroll
        for (int j = 0; j < 16; j++) att2[j] = pack2(att[2*j], att[2*j+1]);

        // ---- Phase C: ao[h*32+d][n] = sum_m att[m] * v[h,d,m] (packed reduction) ----
#pragma unroll 2
        for (int d = 0; d < 32; d++) {
            const ulonglong2* vr = (const ulonglong2*)(qk + (256 + h * 32 + d) * 36);
            u64 sa = 0ull, sb = 0ull;
#pragma unroll
            for (int j = 0; j < 8; j++) {
                ulonglong2 vv = vr[j];
                sa = ffma2(att2[2*j+0], vv.x, sa);
                sb = ffma2(att2[2*j+1], vv.y, sb);
            }
            float a0, a1, b0, b1;
            unpack2(sa, a0, a1); unpack2(sb, b0, b1);
            ao[(h * 32 + d) * 36 + lane] = (a0 + a1) + (b0 + b1);
        }
    }
    __syncthreads();

    // ---- Phase D: y = out_w @ ao + out_b + x ; BN partial stats (packed) ----
    {
        int o = tid;
        float ob = out_b[o];
        u64 acc2[16];
        u64 ob2 = pack2(ob, ob);
#pragma unroll
        for (int j = 0; j < 16; j++) acc2[j] = ob2;
#pragma unroll 4
        for (int c = 0; c < CH; c++) {
            float w = g_out_wT[c * CH + o];
            u64 w2 = pack2(w, w);
            const ulonglong2* ar = (const ulonglong2*)(ao + c * 36);
#pragma unroll
            for (int j = 0; j < 8; j++) {
                ulonglong2 av = ar[j];
                acc2[2*j+0] = ffma2(w2, av.x, acc2[2*j+0]);
                acc2[2*j+1] = ffma2(w2, av.y, acc2[2*j+1]);
            }
        }
        u64 s1_2 = 0ull, s2_2 = 0ull;
        const ulonglong2* xr = (const ulonglong2*)(xs + o * 36);
        ulonglong2* yd = (ulonglong2*)(ys + o * 36);
#pragma unroll
        for (int j = 0; j < 8; j++) {
            ulonglong2 xv = xr[j];
            u64 y0 = fadd2(acc2[2*j+0], xv.x);
            u64 y1 = fadd2(acc2[2*j+1], xv.y);
            s1_2 = fadd2(s1_2, fadd2(y0, y1));
            s2_2 = ffma2(y0, y0, s2_2);
            s2_2 = ffma2(y1, y1, s2_2);
            yd[j] = make_ulonglong2(y0, y1);
        }
        float p0, p1, q0, q1;
        unpack2(s1_2, p0, p1); unpack2(s2_2, q0, q1);
        atomicAdd(&g_bn_sum[o], (double)(p0 + p1));
        atomicAdd(&g_bn_sqs[o], (double)(q0 + q1));
    }
    __syncthreads();

    // ---- coalesced write of pre-BN y to gmem ----
    float4* og = (float4*)(out + (size_t)b * (CH * NB));
#pragma unroll
    for (int k = 0; k < 8; k++) {
        int f = tid + k * 128;
        int c = f >> 3, n4 = f & 7;
        og[f] = *(const float4*)(ys + c * 36 + n4 * 4);
    }
}

__global__ void bn_finalize(const float* __restrict__ gamma,
                            const float* __restrict__ beta) {
    int c = threadIdx.x;
    const double cnt = (double)BATCH * NB;
    double mean = g_bn_sum[c] / cnt;
    double var  = g_bn_sqs[c] / cnt - mean * mean;
    double inv  = 1.0 / sqrt(var + 1e-5);
    double g = (double)gamma[c] * inv;
    g_bn_g[c] = (float)g;
    g_bn_b[c] = (float)((double)beta[c] - mean * g);
}

__global__ void bn_apply(float* __restrict__ out) {
    int i = blockIdx.x * blockDim.x + threadIdx.x;
    float4 v = ((const float4*)out)[i];
    int c = (i >> 3) & 127;
    float g = g_bn_g[c], b = g_bn_b[c];
    v.x = fmaf(v.x, g, b);
    v.y = fmaf(v.y, g, b);
    v.z = fmaf(v.z, g, b);
    v.w = fmaf(v.w, g, b);
    ((float4*)out)[i] = v;
}

extern "C" void kernel_launch(void* const* d_in, const int* in_sizes, int n_in,
                              void* d_out, int out_size) {
    const float* x      = (const float*)d_in[0];
    const float* qkv_w  = (const float*)d_in[1];
    const float* qkv_b  = (const float*)d_in[2];
    const float* out_w  = (const float*)d_in[3];
    const float* out_b  = (const float*)d_in[4];
    const float* remb   = (const float*)d_in[5];
    const float* gamma  = (const float*)d_in[6];
    const float* beta   = (const float*)d_in[7];
    float* out = (float*)d_out;

    cudaFuncSetAttribute(attn_kernel, cudaFuncAttributeMaxDynamicSharedMemorySize,
                         SMEM_FLOATS * (int)sizeof(float));

    prep_kernel<<<192, 256>>>(qkv_w, out_w);
    attn_kernel<<<BATCH, 128, SMEM_FLOATS * sizeof(float)>>>(x, qkv_b, out_b, remb, out);
    bn_finalize<<<1, CH>>>(gamma, beta);
    bn_apply<<<(BATCH * CH * NB / 4) / 256, 256>>>(out);
}

// round 4
// speedup vs baseline: 1.2319x; 1.0854x over previous
#include <cuda_runtime.h>
#include <math.h>

#define BATCH 8192
#define CH 128
#define NB 32
#define NH 4
#define HD 32
#define O3 384
#define ATT_SCALE 0.17677669529663687f  // 1/sqrt(32)

typedef unsigned long long u64;

__device__ __forceinline__ u64 pack2(float lo, float hi) {
    u64 r; asm("mov.b64 %0, {%1, %2};" : "=l"(r) : "f"(lo), "f"(hi)); return r;
}
__device__ __forceinline__ void unpack2(u64 v, float& lo, float& hi) {
    asm("mov.b64 {%0, %1}, %2;" : "=f"(lo), "=f"(hi) : "l"(v));
}
__device__ __forceinline__ u64 ffma2(u64 a, u64 b, u64 c) {
    u64 d; asm("fma.rn.f32x2 %0, %1, %2, %3;" : "=l"(d) : "l"(a), "l"(b), "l"(c)); return d;
}
__device__ __forceinline__ u64 fadd2(u64 a, u64 b) {
    u64 d; asm("add.rn.f32x2 %0, %1, %2;" : "=l"(d) : "l"(a), "l"(b)); return d;
}

// ---- device scratch (no allocations allowed) ----
__device__ float  g_qkv_wT[CH * O3];   // [c][o]
__device__ float  g_out_wT[CH * CH];   // [c][o]
__device__ double g_bn_sum[CH];
__device__ double g_bn_sqs[CH];
__device__ float  g_bn_g[CH];
__device__ float  g_bn_b[CH];

__global__ void prep_kernel(const float* __restrict__ qkv_w,
                            const float* __restrict__ out_w) {
    int i = blockIdx.x * blockDim.x + threadIdx.x;
    if (i < O3 * CH) {
        int o = i / CH, c = i % CH;
        g_qkv_wT[c * O3 + o] = qkv_w[i];
    }
    if (i < CH * CH) {
        int o = i / CH, c = i % CH;
        g_out_wT[c * CH + o] = out_w[i];
    }
    if (i < CH) { g_bn_sum[i] = 0.0; g_bn_sqs[i] = 0.0; }
}

// Shared memory layout (floats). Row stride 36 floats = 144B (16B aligned).
// Aliasing (for occupancy): ys == xs (residual read-then-overwrite, same
// thread); ao == q rows of qk (warp h reads its q rows into registers before
// it writes ao rows h*32..h*32+31 — exactly the same rows, warp-private).
#define XS_OFF   0        // xs [128][36]; later reused as ys
#define QK_OFF   4608     // qk [384][36]; q:0-127 (later reused as ao), k:128-255, v:256-383
#define RP_OFF   18432    // rp [4][63]
#define SMEM_FLOATS 18688 // 74,752 bytes -> 3 CTAs/SM

__global__ void __launch_bounds__(128, 3)
attn_kernel(const float* __restrict__ x,
            const float* __restrict__ qkv_b,
            const float* __restrict__ out_b,
            const float* __restrict__ remb,
            float* __restrict__ out) {
    extern __shared__ float sm[];
    float* xs = sm + XS_OFF;
    float* qk = sm + QK_OFF;
    float* ao = sm + QK_OFF;   // aliases q rows (0..127) of qk
    float* ys = sm + XS_OFF;   // aliases xs
    float* rp = sm + RP_OFF;

    const int tid  = threadIdx.x;
    const int lane = tid & 31;
    const int wid  = tid >> 5;
    const int b    = blockIdx.x;

    // ---- stage x[b] into smem ----
    const float4* xg = (const float4*)(x + (size_t)b * (CH * NB));
#pragma unroll
    for (int k = 0; k < 8; k++) {
        int f = tid + k * 128;
        float4 v = xg[f];
        int c = f >> 3, n4 = f & 7;
        *(float4*)(xs + c * 36 + n4 * 4) = v;
    }
    for (int i = tid; i < (2 * NB - 1) * NH; i += 128) {
        int p = i >> 2, h = i & 3;
        rp[h * 63 + p] = remb[i];
    }
    __syncthreads();

    // ---- Phase A: qkv[o][n] = sum_c W[o][c] * x[c][n] + b[o]  (packed f32x2) ----
    for (int t = wid; t < 12; t += 4) {
        int o = t * 32 + lane;
        float bias = qkv_b[o];
        u64 acc2[16];
        u64 b2 = pack2(bias, bias);
#pragma unroll
        for (int j = 0; j < 16; j++) acc2[j] = b2;
#pragma unroll 4
        for (int c = 0; c < CH; c++) {
            float w = g_qkv_wT[c * O3 + o];                       // coalesced LDG
            u64 w2 = pack2(w, w);
            const ulonglong2* xr = (const ulonglong2*)(xs + c * 36); // LDS.128 broadcast
#pragma unroll
            for (int j = 0; j < 8; j++) {
                ulonglong2 xv = xr[j];
                acc2[2*j+0] = ffma2(w2, xv.x, acc2[2*j+0]);
                acc2[2*j+1] = ffma2(w2, xv.y, acc2[2*j+1]);
            }
        }
        ulonglong2* dst = (ulonglong2*)(qk + o * 36);
#pragma unroll
        for (int j = 0; j < 8; j++)
            dst[j] = make_ulonglong2(acc2[2*j], acc2[2*j+1]);
    }
    __syncthreads();

    // ---- Phase B: head h = wid, query bin n = lane ----
    {
        int h = wid;
        float qreg[32];
#pragma unroll
        for (int d = 0; d < 32; d++)
            qreg[d] = qk[(h * 32 + d) * 36 + lane];               // conflict-free
        u64 att2[16];
#pragma unroll
        for (int j = 0; j < 16; j++) att2[j] = 0ull;
#pragma unroll 4
        for (int d = 0; d < 32; d++) {
            u64 qd2 = pack2(qreg[d], qreg[d]);
            const ulonglong2* kr = (const ulonglong2*)(qk + (128 + h * 32 + d) * 36);
#pragma unroll
            for (int j = 0; j < 8; j++) {
                ulonglong2 kv = kr[j];
                att2[2*j+0] = ffma2(qd2, kv.x, att2[2*j+0]);
                att2[2*j+1] = ffma2(qd2, kv.y, att2[2*j+1]);
            }
        }
        float att[32];
#pragma unroll
        for (int j = 0; j < 16; j++) unpack2(att2[j], att[2*j], att[2*j+1]);
#pragma unroll
        for (int m = 0; m < 32; m++) {
            int idx = m - lane + (NB - 1);
            idx = idx < 0 ? 0 : (idx > 2 * NB - 2 ? 2 * NB - 2 : idx);
            att[m] = fmaf(att[m], ATT_SCALE, rp[h * 63 + idx]);
        }
        float mx = att[0];
#pragma unroll
        for (int m = 1; m < 32; m++) mx = fmaxf(mx, att[m]);
        float ssum = 0.0f;
#pragma unroll
        for (int m = 0; m < 32; m++) {
            float e = __expf(att[m] - mx);
            att[m] = e;
            ssum += e;
        }
        float rs = 1.0f / ssum;
#pragma unroll
        for (int m = 0; m < 32; m++) att[m] *= rs;
#pragma unroll
        for (int j = 0; j < 16; j++) att2[j] = pack2(att[2*j], att[2*j+1]);

        // ---- Phase C: ao[h*32+d][n] = sum_m att[m] * v[h,d,m] (packed reduction) ----
        // Writes alias this warp's own q rows; q already consumed into qreg.
#pragma unroll 2
        for (int d = 0; d < 32; d++) {
            const ulonglong2* vr = (const ulonglong2*)(qk + (256 + h * 32 + d) * 36);
            u64 sa = 0ull, sb = 0ull;
#pragma unroll
            for (int j = 0; j < 8; j++) {
                ulonglong2 vv = vr[j];
                sa = ffma2(att2[2*j+0], vv.x, sa);
                sb = ffma2(att2[2*j+1], vv.y, sb);
            }
            float a0, a1, b0, b1;
            unpack2(sa, a0, a1); unpack2(sb, b0, b1);
            ao[(h * 32 + d) * 36 + lane] = (a0 + a1) + (b0 + b1);
        }
    }
    __syncthreads();

    // ---- Phase D: y = out_w @ ao + out_b + x ; BN partial stats (packed) ----
    {
        int o = tid;
        float ob = out_b[o];
        u64 acc2[16];
        u64 ob2 = pack2(ob, ob);
#pragma unroll
        for (int j = 0; j < 16; j++) acc2[j] = ob2;
#pragma unroll 4
        for (int c = 0; c < CH; c++) {
            float w = g_out_wT[c * CH + o];
            u64 w2 = pack2(w, w);
            const ulonglong2* ar = (const ulonglong2*)(ao + c * 36);
#pragma unroll
            for (int j = 0; j < 8; j++) {
                ulonglong2 av = ar[j];
                acc2[2*j+0] = ffma2(w2, av.x, acc2[2*j+0]);
                acc2[2*j+1] = ffma2(w2, av.y, acc2[2*j+1]);
            }
        }
        u64 s1_2 = 0ull, s2_2 = 0ull;
        const ulonglong2* xr = (const ulonglong2*)(xs + o * 36);
        ulonglong2* yd = (ulonglong2*)(ys + o * 36);   // same address as xr: read-then-write
#pragma unroll
        for (int j = 0; j < 8; j++) {
            ulonglong2 xv = xr[j];
            u64 y0 = fadd2(acc2[2*j+0], xv.x);
            u64 y1 = fadd2(acc2[2*j+1], xv.y);
            s1_2 = fadd2(s1_2, fadd2(y0, y1));
            s2_2 = ffma2(y0, y0, s2_2);
            s2_2 = ffma2(y1, y1, s2_2);
            yd[j] = make_ulonglong2(y0, y1);
        }
        float p0, p1, q0, q1;
        unpack2(s1_2, p0, p1); unpack2(s2_2, q0, q1);
        atomicAdd(&g_bn_sum[o], (double)(p0 + p1));
        atomicAdd(&g_bn_sqs[o], (double)(q0 + q1));
    }
    __syncthreads();

    // ---- coalesced write of pre-BN y to gmem ----
    float4* og = (float4*)(out + (size_t)b * (CH * NB));
#pragma unroll
    for (int k = 0; k < 8; k++) {
        int f = tid + k * 128;
        int c = f >> 3, n4 = f & 7;
        og[f] = *(const float4*)(ys + c * 36 + n4 * 4);
    }
}

__global__ void bn_finalize(const float* __restrict__ gamma,
                            const float* __restrict__ beta) {
    int c = threadIdx.x;
    const double cnt = (double)BATCH * NB;
    double mean = g_bn_sum[c] / cnt;
    double var  = g_bn_sqs[c] / cnt - mean * mean;
    double inv  = 1.0 / sqrt(var + 1e-5);
    double g = (double)gamma[c] * inv;
    g_bn_g[c] = (float)g;
    g_bn_b[c] = (float)((double)beta[c] - mean * g);
}

__global__ void bn_apply(float* __restrict__ out) {
    int i = blockIdx.x * blockDim.x + threadIdx.x;
    float4 v = ((const float4*)out)[i];
    int c = (i >> 3) & 127;
    float g = g_bn_g[c], b = g_bn_b[c];
    v.x = fmaf(v.x, g, b);
    v.y = fmaf(v.y, g, b);
    v.z = fmaf(v.z, g, b);
    v.w = fmaf(v.w, g, b);
    ((float4*)out)[i] = v;
}

extern "C" void kernel_launch(void* const* d_in, const int* in_sizes, int n_in,
                              void* d_out, int out_size) {
    const float* x      = (const float*)d_in[0];
    const float* qkv_w  = (const float*)d_in[1];
    const float* qkv_b  = (const float*)d_in[2];
    const float* out_w  = (const float*)d_in[3];
    const float* out_b  = (const float*)d_in[4];
    const float* remb   = (const float*)d_in[5];
    const float* gamma  = (const float*)d_in[6];
    const float* beta   = (const float*)d_in[7];
    float* out = (float*)d_out;

    cudaFuncSetAttribute(attn_kernel, cudaFuncAttributeMaxDynamicSharedMemorySize,
                         SMEM_FLOATS * (int)sizeof(float));

    prep_kernel<<<192, 256>>>(qkv_w, out_w);
    attn_kernel<<<BATCH, 128, SMEM_FLOATS * sizeof(float)>>>(x, qkv_b, out_b, remb, out);
    bn_finalize<<<1, CH>>>(gamma, beta);
    bn_apply<<<(BATCH * CH * NB / 4) / 256, 256>>>(out);
}

// round 5
// speedup vs baseline: 1.4976x; 1.2157x over previous
#include <cuda_runtime.h>
#include <math.h>

#define BATCH 8192
#define CH 128
#define NB 32
#define NH 4
#define HD 32
#define O3 384
#define ATT_SCALE 0.17677669529663687f  // 1/sqrt(32)

typedef unsigned long long u64;

__device__ __forceinline__ u64 pack2(float lo, float hi) {
    u64 r; asm("mov.b64 %0, {%1, %2};" : "=l"(r) : "f"(lo), "f"(hi)); return r;
}
__device__ __forceinline__ void unpack2(u64 v, float& lo, float& hi) {
    asm("mov.b64 {%0, %1}, %2;" : "=f"(lo), "=f"(hi) : "l"(v));
}
__device__ __forceinline__ u64 ffma2(u64 a, u64 b, u64 c) {
    u64 d; asm("fma.rn.f32x2 %0, %1, %2, %3;" : "=l"(d) : "l"(a), "l"(b), "l"(c)); return d;
}
__device__ __forceinline__ u64 fadd2(u64 a, u64 b) {
    u64 d; asm("add.rn.f32x2 %0, %1, %2;" : "=l"(d) : "l"(a), "l"(b)); return d;
}

// ---- device scratch (no allocations allowed) ----
// Weights stored PRE-DUPLICATED as u64 {w,w}: one LDG.64, zero packing movs.
__device__ u64    g_qkv_w2[CH * O3];   // [c][o] -> {w,w}
__device__ u64    g_out_w2[CH * CH];   // [c][o] -> {w,w}
__device__ double g_bn_sum[CH];
__device__ double g_bn_sqs[CH];
__device__ float  g_bn_g[CH];
__device__ float  g_bn_b[CH];

__global__ void prep_kernel(const float* __restrict__ qkv_w,
                            const float* __restrict__ out_w) {
    int i = blockIdx.x * blockDim.x + threadIdx.x;
    if (i < O3 * CH) {
        int o = i / CH, c = i % CH;
        float w = qkv_w[i];
        g_qkv_w2[c * O3 + o] = pack2(w, w);
    }
    if (i < CH * CH) {
        int o = i / CH, c = i % CH;
        float w = out_w[i];
        g_out_w2[c * CH + o] = pack2(w, w);
    }
    if (i < CH) { g_bn_sum[i] = 0.0; g_bn_sqs[i] = 0.0; }
}

// Shared memory layout (floats). Row stride 36 floats = 144B (16B aligned).
// Aliasing: ys == xs (same-thread read-then-overwrite); ao == q rows of qk
// (warp h consumes its q rows into registers before overwriting them).
#define XS_OFF   0        // xs [128][36]; later reused as ys
#define QK_OFF   4608     // qk [384][36]; q:0-127 (later reused as ao), k:128-255, v:256-383
#define RP_OFF   18432    // rp [4][63]
#define SMEM_FLOATS 18688 // 74,752 bytes -> 3 CTAs/SM

__global__ void __launch_bounds__(128, 3)
attn_kernel(const float* __restrict__ x,
            const float* __restrict__ qkv_b,
            const float* __restrict__ out_b,
            const float* __restrict__ remb,
            float* __restrict__ out) {
    extern __shared__ float sm[];
    float* xs = sm + XS_OFF;
    float* qk = sm + QK_OFF;
    float* ao = sm + QK_OFF;   // aliases q rows (0..127) of qk
    float* ys = sm + XS_OFF;   // aliases xs
    float* rp = sm + RP_OFF;

    const int tid  = threadIdx.x;
    const int lane = tid & 31;
    const int wid  = tid >> 5;
    const int b    = blockIdx.x;

    // ---- stage x[b] into smem ----
    const float4* xg = (const float4*)(x + (size_t)b * (CH * NB));
#pragma unroll
    for (int k = 0; k < 8; k++) {
        int f = tid + k * 128;
        float4 v = xg[f];
        int c = f >> 3, n4 = f & 7;
        *(float4*)(xs + c * 36 + n4 * 4) = v;
    }
    for (int i = tid; i < (2 * NB - 1) * NH; i += 128) {
        int p = i >> 2, h = i & 3;
        rp[h * 63 + p] = remb[i];
    }
    __syncthreads();

    // ---- Phase A (fused q/k/v): one pass over c, 8 LDS feed 48 FFMA2 ----
    {
        const int o = wid * 32 + lane;           // q row; k = o+128; v = o+256
        u64 accq[16], acck[16], accv[16];
        {
            float bq = qkv_b[o], bk = qkv_b[o + 128], bv = qkv_b[o + 256];
            u64 q2 = pack2(bq, bq), k2 = pack2(bk, bk), v2 = pack2(bv, bv);
#pragma unroll
            for (int j = 0; j < 16; j++) { accq[j] = q2; acck[j] = k2; accv[j] = v2; }
        }
#pragma unroll 2
        for (int c = 0; c < CH; c++) {
            u64 wq = g_qkv_w2[c * O3 + o];             // coalesced LDG.64
            u64 wk = g_qkv_w2[c * O3 + o + 128];
            u64 wv = g_qkv_w2[c * O3 + o + 256];
            const ulonglong2* xr = (const ulonglong2*)(xs + c * 36); // LDS.128 broadcast
#pragma unroll
            for (int j = 0; j < 8; j++) {
                ulonglong2 xv = xr[j];
                accq[2*j+0] = ffma2(wq, xv.x, accq[2*j+0]);
                accq[2*j+1] = ffma2(wq, xv.y, accq[2*j+1]);
                acck[2*j+0] = ffma2(wk, xv.x, acck[2*j+0]);
                acck[2*j+1] = ffma2(wk, xv.y, acck[2*j+1]);
                accv[2*j+0] = ffma2(wv, xv.x, accv[2*j+0]);
                accv[2*j+1] = ffma2(wv, xv.y, accv[2*j+1]);
            }
        }
        ulonglong2* dq = (ulonglong2*)(qk + o * 36);
        ulonglong2* dk = (ulonglong2*)(qk + (o + 128) * 36);
        ulonglong2* dv = (ulonglong2*)(qk + (o + 256) * 36);
#pragma unroll
        for (int j = 0; j < 8; j++) {
            dq[j] = make_ulonglong2(accq[2*j], accq[2*j+1]);
            dk[j] = make_ulonglong2(acck[2*j], acck[2*j+1]);
            dv[j] = make_ulonglong2(accv[2*j], accv[2*j+1]);
        }
    }
    __syncthreads();

    // ---- Phase B: head h = wid, query bin n = lane ----
    {
        int h = wid;
        float qreg[32];
#pragma unroll
        for (int d = 0; d < 32; d++)
            qreg[d] = qk[(h * 32 + d) * 36 + lane];               // conflict-free
        u64 att2[16];
#pragma unroll
        for (int j = 0; j < 16; j++) att2[j] = 0ull;
#pragma unroll 4
        for (int d = 0; d < 32; d++) {
            u64 qd2 = pack2(qreg[d], qreg[d]);
            const ulonglong2* kr = (const ulonglong2*)(qk + (128 + h * 32 + d) * 36);
#pragma unroll
            for (int j = 0; j < 8; j++) {
                ulonglong2 kv = kr[j];
                att2[2*j+0] = ffma2(qd2, kv.x, att2[2*j+0]);
                att2[2*j+1] = ffma2(qd2, kv.y, att2[2*j+1]);
            }
        }
        float att[32];
#pragma unroll
        for (int j = 0; j < 16; j++) unpack2(att2[j], att[2*j], att[2*j+1]);
#pragma unroll
        for (int m = 0; m < 32; m++) {
            int idx = m - lane + (NB - 1);
            idx = idx < 0 ? 0 : (idx > 2 * NB - 2 ? 2 * NB - 2 : idx);
            att[m] = fmaf(att[m], ATT_SCALE, rp[h * 63 + idx]);
        }
        float mx = att[0];
#pragma unroll
        for (int m = 1; m < 32; m++) mx = fmaxf(mx, att[m]);
        float ssum = 0.0f;
#pragma unroll
        for (int m = 0; m < 32; m++) {
            float e = __expf(att[m] - mx);
            att[m] = e;
            ssum += e;
        }
        float rs = 1.0f / ssum;
#pragma unroll
        for (int m = 0; m < 32; m++) att[m] *= rs;
#pragma unroll
        for (int j = 0; j < 16; j++) att2[j] = pack2(att[2*j], att[2*j+1]);

        // ---- Phase C: ao[h*32+d][n] = sum_m att[m] * v[h,d,m] ----
        // Writes alias this warp's own q rows; q already consumed into qreg.
#pragma unroll 2
        for (int d = 0; d < 32; d++) {
            const ulonglong2* vr = (const ulonglong2*)(qk + (256 + h * 32 + d) * 36);
            u64 sa = 0ull, sb = 0ull;
#pragma unroll
            for (int j = 0; j < 8; j++) {
                ulonglong2 vv = vr[j];
                sa = ffma2(att2[2*j+0], vv.x, sa);
                sb = ffma2(att2[2*j+1], vv.y, sb);
            }
            float a0, a1, b0, b1;
            unpack2(sa, a0, a1); unpack2(sb, b0, b1);
            ao[(h * 32 + d) * 36 + lane] = (a0 + a1) + (b0 + b1);
        }
    }
    __syncthreads();

    // ---- Phase D: y = out_w @ ao + out_b + x ; BN partial stats ----
    {
        int o = tid;
        float ob = out_b[o];
        u64 acc2[16];
        u64 ob2 = pack2(ob, ob);
#pragma unroll
        for (int j = 0; j < 16; j++) acc2[j] = ob2;
#pragma unroll 4
        for (int c = 0; c < CH; c++) {
            u64 w2 = g_out_w2[c * CH + o];                       // LDG.64, no mov
            const ulonglong2* ar = (const ulonglong2*)(ao + c * 36);
#pragma unroll
            for (int j = 0; j < 8; j++) {
                ulonglong2 av = ar[j];
                acc2[2*j+0] = ffma2(w2, av.x, acc2[2*j+0]);
                acc2[2*j+1] = ffma2(w2, av.y, acc2[2*j+1]);
            }
        }
        u64 s1_2 = 0ull, s2_2 = 0ull;
        const ulonglong2* xr = (const ulonglong2*)(xs + o * 36);
        ulonglong2* yd = (ulonglong2*)(ys + o * 36);   // same address: read-then-write
#pragma unroll
        for (int j = 0; j < 8; j++) {
            ulonglong2 xv = xr[j];
            u64 y0 = fadd2(acc2[2*j+0], xv.x);
            u64 y1 = fadd2(acc2[2*j+1], xv.y);
            s1_2 = fadd2(s1_2, fadd2(y0, y1));
            s2_2 = ffma2(y0, y0, s2_2);
            s2_2 = ffma2(y1, y1, s2_2);
            yd[j] = make_ulonglong2(y0, y1);
        }
        float p0, p1, q0, q1;
        unpack2(s1_2, p0, p1); unpack2(s2_2, q0, q1);
        atomicAdd(&g_bn_sum[o], (double)(p0 + p1));
        atomicAdd(&g_bn_sqs[o], (double)(q0 + q1));
    }
    __syncthreads();

    // ---- coalesced write of pre-BN y to gmem ----
    float4* og = (float4*)(out + (size_t)b * (CH * NB));
#pragma unroll
    for (int k = 0; k < 8; k++) {
        int f = tid + k * 128;
        int c = f >> 3, n4 = f & 7;
        og[f] = *(const float4*)(ys + c * 36 + n4 * 4);
    }
}

__global__ void bn_finalize(const float* __restrict__ gamma,
                            const float* __restrict__ beta) {
    int c = threadIdx.x;
    const double cnt = (double)BATCH * NB;
    double mean = g_bn_sum[c] / cnt;
    double var  = g_bn_sqs[c] / cnt - mean * mean;
    double inv  = 1.0 / sqrt(var + 1e-5);
    double g = (double)gamma[c] * inv;
    g_bn_g[c] = (float)g;
    g_bn_b[c] = (float)((double)beta[c] - mean * g);
}

__global__ void bn_apply(float* __restrict__ out) {
    int i = blockIdx.x * blockDim.x + threadIdx.x;
    float4 v = ((const float4*)out)[i];
    int c = (i >> 3) & 127;
    float g = g_bn_g[c], b = g_bn_b[c];
    v.x = fmaf(v.x, g, b);
    v.y = fmaf(v.y, g, b);
    v.z = fmaf(v.z, g, b);
    v.w = fmaf(v.w, g, b);
    ((float4*)out)[i] = v;
}

extern "C" void kernel_launch(void* const* d_in, const int* in_sizes, int n_in,
                              void* d_out, int out_size) {
    const float* x      = (const float*)d_in[0];
    const float* qkv_w  = (const float*)d_in[1];
    const float* qkv_b  = (const float*)d_in[2];
    const float* out_w  = (const float*)d_in[3];
    const float* out_b  = (const float*)d_in[4];
    const float* remb   = (const float*)d_in[5];
    const float* gamma  = (const float*)d_in[6];
    const float* beta   = (const float*)d_in[7];
    float* out = (float*)d_out;

    cudaFuncSetAttribute(attn_kernel, cudaFuncAttributeMaxDynamicSharedMemorySize,
                         SMEM_FLOATS * (int)sizeof(float));

    prep_kernel<<<192, 256>>>(qkv_w, out_w);
    attn_kernel<<<BATCH, 128, SMEM_FLOATS * sizeof(float)>>>(x, qkv_b, out_b, remb, out);
    bn_finalize<<<1, CH>>>(gamma, beta);
    bn_apply<<<(BATCH * CH * NB / 4) / 256, 256>>>(out);
}